// round 7
// baseline (speedup 1.0000x reference)
#include <cuda_runtime.h>
#include <stdint.h>

// TopKTokenChoiceRouter: x(8192,4096) fp32 @ W^T(4096,64) -> softmax -> top2.
// 3xTF32 mma.sync.m16n8k8 (compute_100-safe). R7: fragment-order W (LDS.128 B
// loads), 512 threads (16 warps), single sync per chunk.
// Out layout (validated): [weights M*2 f32][indices-as-f32 M*2].

#define K_DIM   4096
#define NE      64
#define BM      128
#define BK      32
#define NSPLIT  2
#define KSPLIT  (K_DIM / NSPLIT)      // 2048
#define NCH     (KSPLIT / BK)         // 64 chunks per split
#define NCHTOT  (K_DIM / BK)          // 128 chunks total
#define NSTAGE  4
#define MMAX    8192

#define ROWSTR  36                    // A row stride (floats), conflict-free frags
#define A_BYTES (BM * ROWSTR * 4)     // 18432
#define B_BYTES 16384                 // 1024 x 16B frag records per chunk
#define OFF_B   A_BYTES
#define STAGE_BYTES (A_BYTES + B_BYTES)              // 34816
#define SMEM_TOTAL (NSTAGE * STAGE_BYTES)            // 139264

typedef unsigned int u32;

__device__ float g_partials[(size_t)NSPLIT * MMAX * NE];   // 4 MB
__device__ uint4 g_Wfrag[(size_t)NCHTOT * 1024];           // 2 MB, fragment order

__device__ __forceinline__ u32 smem_u32(const void* p){
    u32 a; asm("{ .reg .u64 t; cvta.to.shared.u64 t, %1; cvt.u32.u64 %0, t; }" : "=r"(a) : "l"(p));
    return a;
}
__device__ __forceinline__ void split_tf32(float v, u32& hi, u32& lo){
    asm("cvt.rna.tf32.f32 %0, %1;" : "=r"(hi) : "f"(v));
    float r = v - __uint_as_float(hi);
    asm("cvt.rna.tf32.f32 %0, %1;" : "=r"(lo) : "f"(r));
}
__device__ __forceinline__ void cpa16(u32 dst, const void* src){
    asm volatile("cp.async.ca.shared.global [%0], [%1], 16;" :: "r"(dst), "l"(src));
}
__device__ __forceinline__ void cpa_commit(){
    asm volatile("cp.async.commit_group;" ::: "memory");
}
template<int N> __device__ __forceinline__ void cpa_wait(){
    asm volatile("cp.async.wait_group %0;" :: "n"(N) : "memory");
}
__device__ __forceinline__ float lds32(u32 a){
    float v; asm volatile("ld.shared.f32 %0, [%1];" : "=f"(v) : "r"(a));
    return v;
}
__device__ __forceinline__ uint4 lds128(u32 a){
    uint4 v;
    asm volatile("ld.shared.v4.b32 {%0,%1,%2,%3}, [%4];"
                 : "=r"(v.x), "=r"(v.y), "=r"(v.z), "=r"(v.w) : "r"(a));
    return v;
}
__device__ __forceinline__ void mma8(float (&d)[4], const u32 (&a)[4], u32 b0, u32 b1){
    asm volatile("mma.sync.aligned.m16n8k8.row.col.f32.tf32.tf32.f32 "
        "{%0,%1,%2,%3}, {%4,%5,%6,%7}, {%8,%9}, {%0,%1,%2,%3};"
        : "+f"(d[0]), "+f"(d[1]), "+f"(d[2]), "+f"(d[3])
        : "r"(a[0]), "r"(a[1]), "r"(a[2]), "r"(a[3]), "r"(b0), "r"(b1));
}

// ---------------- W pre-split into fragment order ----------------
// Record gid = ch*1024 + n*16 + ks*4 + lk  ->  {hi(k0), hi(k0+4), lo(k0), lo(k0+4)},
// k0 = ch*32 + ks*8 + lk. In-GEMM read addr for warp lane: (nf*32 + lane)*16B.
__global__ __launch_bounds__(256) void conv_w_kernel(const float* __restrict__ W){
    const int gid = blockIdx.x * 256 + threadIdx.x;     // 0 .. 131071
    const int ch  = gid >> 10;
    const int rem = gid & 1023;
    const int n   = rem >> 4;
    const int ks  = (rem >> 2) & 3;
    const int lk  = rem & 3;
    const int k0  = ch * BK + ks * 8 + lk;
    const float* wr = W + (size_t)n * K_DIM;
    uint4 o;
    u32 l0, l1;
    split_tf32(wr[k0],     o.x, l0);
    split_tf32(wr[k0 + 4], o.y, l1);
    o.z = l0; o.w = l1;
    g_Wfrag[gid] = o;
}

// ---------------- GEMM (split-K, 3xTF32) ----------------
__global__ __launch_bounds__(512, 1) void gemm_kernel(
    const float* __restrict__ x, int M)
{
    extern __shared__ char smem[];
    const u32 sbase = smem_u32(smem);
    const int tid  = threadIdx.x;
    const int wid  = tid >> 5;
    const int lane = tid & 31;
    const int m_base = blockIdx.x * BM;
    const int split  = blockIdx.y;
    const int k0     = split * KSPLIT;

    // cp.async: A 1024 float4/stage (2/thread), B 1024 uint4/stage (2/thread)
    const float* srcA[2]; u32 dstA[2];
    #pragma unroll
    for (int i = 0; i < 2; i++) {
        const int idx = tid + 512 * i;
        const int row = idx >> 3, f4 = idx & 7;
        srcA[i] = x + (size_t)(m_base + row) * K_DIM + k0 + f4 * 4;
        dstA[i] = row * (ROWSTR * 4) + f4 * 16;
    }
    const uint4* srcB = g_Wfrag + (size_t)split * NCH * 1024 + tid;

    #define ISSUE_STAGE(ch) do {                                              \
        const u32 st = sbase + ((ch) & (NSTAGE - 1)) * STAGE_BYTES;           \
        _Pragma("unroll")                                                     \
        for (int i = 0; i < 2; i++) {                                         \
            cpa16(st + dstA[i], srcA[i] + (ch) * BK);                         \
            cpa16(st + OFF_B + (u32)(tid + 512 * i) * 16,                     \
                  srcB + (size_t)(ch) * 1024 + 512 * i);                      \
        }                                                                     \
    } while (0)

    ISSUE_STAGE(0); cpa_commit();
    ISSUE_STAGE(1); cpa_commit();
    ISSUE_STAGE(2); cpa_commit();

    float c[4][4];
    #pragma unroll
    for (int j = 0; j < 4; j++)
        #pragma unroll
        for (int q = 0; q < 4; q++) c[j][q] = 0.f;

    const int m0 = (wid >> 1) * 16;               // 8 m-bands
    const int nfBase = (wid & 1) * 4;             // 2 n-halves, 4 nf each
    const u32 aRowOff = (u32)(m0 + (lane >> 2)) * (ROWSTR * 4);
    const u32 aColOff = (u32)(lane & 3) * 4;
    const u32 bLaneOff = OFF_B + (u32)((nfBase * 32 + lane) * 16);

    #pragma unroll 1
    for (int ch = 0; ch < NCH; ch++) {
        cpa_wait<2>();
        __syncthreads();
        // refill slot (ch-1)&3 — all warps finished reading it before the sync
        if (ch + 3 < NCH) ISSUE_STAGE(ch + 3);
        cpa_commit();

        const u32 st = sbase + (ch & (NSTAGE - 1)) * STAGE_BYTES;
        #pragma unroll
        for (int ks = 0; ks < 4; ks++) {
            const u32 aA = st + aRowOff + (u32)ks * 32 + aColOff;
            float a0 = lds32(aA);
            float a1 = lds32(aA + 8 * ROWSTR * 4);
            float a2 = lds32(aA + 16);
            float a3 = lds32(aA + 8 * ROWSTR * 4 + 16);
            u32 ahi[4], alo[4];
            split_tf32(a0, ahi[0], alo[0]);
            split_tf32(a1, ahi[1], alo[1]);
            split_tf32(a2, ahi[2], alo[2]);
            split_tf32(a3, ahi[3], alo[3]);

            const u32 bKs = st + bLaneOff + (u32)ks * 64;   // ks stride = 4 recs*16B... per nf block
            #pragma unroll
            for (int j = 0; j < 4; j++) {
                // record addr: ((nfBase+j)*32 + lane)*16 within chunk, ks folded into lane? no:
                // layout per chunk: [n(64)][ks(4)][lk(4)] -> n*16+ks*4+lk records.
                // warp lane (g=lane>>2 -> n=nf*8+g, lk=lane&3): rec = (nf*8+g)*16 + ks*4 + lk
                const int nf = nfBase + j;
                const u32 bA = st + OFF_B +
                    (u32)(((nf * 8 + (lane >> 2)) * 16 + ks * 4 + (lane & 3)) * 16);
                uint4 b = lds128(bA);
                mma8(c[j], ahi, b.x, b.y);   // hi*hi
                mma8(c[j], ahi, b.z, b.w);   // hi*lo
                mma8(c[j], alo, b.x, b.y);   // lo*hi
            }
            (void)bKs;
        }
    }

    // write partial logits [split][token][expert]
    const int t0  = m_base + m0 + (lane >> 2);
    const int col = (lane & 3) * 2;
    #pragma unroll
    for (int j = 0; j < 4; j++) {
        const int nf = nfBase + j;
        float* p0 = g_partials + ((size_t)split * M + t0) * NE + nf * 8 + col;
        *(float2*)p0            = make_float2(c[j][0], c[j][1]);
        *(float2*)(p0 + 8 * NE) = make_float2(c[j][2], c[j][3]);
    }
    #undef ISSUE_STAGE
}

// ---------------- reduce + softmax + top2 ----------------
__global__ __launch_bounds__(256) void reduce_topk_kernel(
    float* __restrict__ out, int M, int write_idx)
{
    const int warp = threadIdx.x >> 5;
    const int lane = threadIdx.x & 31;
    const int t = blockIdx.x * 8 + warp;
    if (t >= M) return;

    float2 s = make_float2(0.f, 0.f);
    const float* p = g_partials + (size_t)t * NE + 2 * lane;
    #pragma unroll
    for (int si = 0; si < NSPLIT; si++) {
        float2 v = *(const float2*)(p + (size_t)si * M * NE);
        s.x += v.x; s.y += v.y;
    }

    float a1, a2; int i1, i2;
    if (s.x >= s.y) { a1 = s.x; i1 = 2 * lane;     a2 = s.y; i2 = 2 * lane + 1; }
    else            { a1 = s.y; i1 = 2 * lane + 1; a2 = s.x; i2 = 2 * lane;     }

    #pragma unroll
    for (int off = 16; off > 0; off >>= 1) {
        float b1 = __shfl_xor_sync(0xffffffffu, a1, off);
        float b2 = __shfl_xor_sync(0xffffffffu, a2, off);
        int  bi1 = __shfl_xor_sync(0xffffffffu, i1, off);
        int  bi2 = __shfl_xor_sync(0xffffffffu, i2, off);
        if (b1 > a1 || (b1 == a1 && bi1 < i1)) {
            if (b2 > a1 || (b2 == a1 && bi2 < i1)) { a1 = b1; i1 = bi1; a2 = b2; i2 = bi2; }
            else                                   { a2 = a1; i2 = i1;  a1 = b1; i1 = bi1; }
        } else {
            if (b1 > a2 || (b1 == a2 && bi1 < i2)) { a2 = b1; i2 = bi1; }
        }
    }

    float ex = __expf(s.x - a1) + __expf(s.y - a1);
    #pragma unroll
    for (int off = 16; off > 0; off >>= 1)
        ex += __shfl_xor_sync(0xffffffffu, ex, off);

    if (lane == 0) {
        const float inv = 1.0f / ex;
        out[2 * t + 0] = inv;
        out[2 * t + 1] = __expf(a2 - a1) * inv;
        if (write_idx) {
            out[2 * M + 2 * t + 0] = (float)i1;
            out[2 * M + 2 * t + 1] = (float)i2;
        }
    }
}

extern "C" void kernel_launch(void* const* d_in, const int* in_sizes, int n_in,
                              void* d_out, int out_size) {
    const float* x = (const float*)d_in[0];   // 8192 x 4096 fp32
    const float* W = (const float*)d_in[1];   // 64 x 4096 fp32
    float* out = (float*)d_out;

    const int M = in_sizes[0] / K_DIM;        // 8192
    const int write_idx = (out_size >= 4 * M) ? 1 : 0;

    cudaFuncSetAttribute(gemm_kernel,
                         cudaFuncAttributeMaxDynamicSharedMemorySize, SMEM_TOTAL);

    conv_w_kernel<<<512, 256>>>(W);
    dim3 grid(M / BM, NSPLIT);
    gemm_kernel<<<grid, 512, SMEM_TOTAL>>>(x, M);
    reduce_topk_kernel<<<(M + 7) / 8, 256>>>(out, M, write_idx);
}